// round 13
// baseline (speedup 1.0000x reference)
#include <cuda_runtime.h>

// out[b, q, dv] = (1/SK) * sum_k value[b, k, dv]
// (q and k are the same broadcast scalar -> all logits equal -> softmax uniform
//  -> output = mean of value over SK, independent of query and q_param.)
//
// Serial read phase -> write phase (overlap measurably degrades combined L2
// throughput on this chip; write path caps at ~2.3 TB/s regardless of store
// mechanism). Final combine is done by the last-arriving reduce CTA per batch
// so broadcast CTAs go straight from PDL sync to stores.

#define B   16
#define SQ  2048
#define SK  2048
#define DV  128
#define SPB 16                   // splits (CTAs) per batch in reduce
#define RPC (SK / SPB)           // 128 rows per reduce CTA

__device__ float4 g_part[B * SPB * 32];   // per-(b,split) partial row (512B)
__device__ float4 g_final[B * 32];        // per-batch final scaled row
__device__ int    g_cnt[B];               // arrival counters (zero-init, self-reset)

// grid (B, SPB) = 256 CTAs, block 512. Each CTA reduces 128 rows.
// Each thread: 8 independent float4 loads, fully unrolled.
// Last arriver per batch combines the 16 partials -> g_final (no spinning).
__global__ void __launch_bounds__(512)
reduce_kernel(const float4* __restrict__ value) {
    const int b   = blockIdx.x;
    const int sp  = blockIdx.y;
    const int tid = threadIdx.x;
    const int dv4 = tid & 31;            // float4 column
    const int rg  = tid >> 5;            // 0..15

    const float4* base = value + ((size_t)b * SK + sp * RPC + rg) * (DV / 4) + dv4;

    float4 v[8];
    #pragma unroll
    for (int k = 0; k < 8; ++k) {
        v[k] = base[(size_t)k * 16 * (DV / 4)];
    }
    float4 s = v[0];
    #pragma unroll
    for (int k = 1; k < 8; ++k) {
        s.x += v[k].x; s.y += v[k].y; s.z += v[k].z; s.w += v[k].w;
    }

    __shared__ float4 tmp[512];
    __shared__ int s_last;
    tmp[tid] = s;
    __syncthreads();

    if (tid < 32) {
        float4 a = tmp[tid];
        #pragma unroll
        for (int g = 1; g < 16; ++g) {
            float4 w = tmp[g * 32 + tid];
            a.x += w.x; a.y += w.y; a.z += w.z; a.w += w.w;
        }
        g_part[(b * SPB + sp) * 32 + tid] = a;
    }
    __syncthreads();

    if (tid == 0) {
        __threadfence();                              // publish my partial
        s_last = (atomicAdd(&g_cnt[b], 1) == SPB - 1);
    }
    __syncthreads();

    if (s_last) {
        if (tid == 0) __threadfence();                // acquire peers' partials
        __syncthreads();
        // 512 threads: 16 splits x 32 columns, one load each
        const int spg = tid >> 5;                     // 0..15
        tmp[tid] = g_part[(b * SPB + spg) * 32 + dv4];
        __syncthreads();
        if (tid < 32) {
            const float inv = 1.0f / (float)SK;
            float4 a = tmp[tid];
            #pragma unroll
            for (int g = 1; g < 16; ++g) {
                float4 w = tmp[g * 32 + tid];
                a.x += w.x; a.y += w.y; a.z += w.z; a.w += w.w;
            }
            a.x *= inv; a.y *= inv; a.z *= inv; a.w *= inv;
            g_final[b * 32 + tid] = a;
        }
        if (tid == 0) g_cnt[b] = 0;                   // self-reset for replay
    }
}

// grid (64, B) = 1024 CTAs, block 256. PDL sync -> load 512B final row ->
// 4 STG.128 per thread (32 output rows per CTA).
__global__ void __launch_bounds__(256)
broadcast_kernel(float4* __restrict__ out) {
    const int b     = blockIdx.y;
    const int chunk = blockIdx.x;         // 32-row chunk
    const int tid   = threadIdx.x;
    const int dv4   = tid & 31;
    const int rg    = tid >> 5;           // 0..7

    __shared__ float4 fin[32];

    float4* o = out + ((size_t)b * SQ + chunk * 32 + rg) * (DV / 4) + dv4;

    cudaGridDependencySynchronize();

    if (tid < 32) fin[tid] = g_final[b * 32 + tid];
    __syncthreads();

    const float4 v = fin[dv4];
    #pragma unroll
    for (int i = 0; i < 4; ++i) {
        o[(size_t)i * 8 * (DV / 4)] = v;
    }
}

extern "C" void kernel_launch(void* const* d_in, const int* in_sizes, int n_in,
                              void* d_out, int out_size) {
    // inputs: query[B,SQ,D], key[B,SK,D], value[B,SK,DV], q_param[1,1]
    const float4* value = (const float4*)d_in[2];
    float4* out = (float4*)d_out;

    {
        dim3 rgrid(B, SPB);
        reduce_kernel<<<rgrid, 512>>>(value);
    }

    {
        cudaLaunchConfig_t cfg = {};
        cfg.gridDim  = dim3(64, B, 1);
        cfg.blockDim = dim3(256, 1, 1);
        cfg.dynamicSmemBytes = 0;
        cfg.stream = 0;

        cudaLaunchAttribute attr[1];
        attr[0].id = cudaLaunchAttributeProgrammaticStreamSerialization;
        attr[0].val.programmaticStreamSerializationAllowed = 1;
        cfg.attrs = attr;
        cfg.numAttrs = 1;

        cudaLaunchKernelEx(&cfg, broadcast_kernel, out);
    }
}

// round 14
// speedup vs baseline: 1.1831x; 1.1831x over previous
#include <cuda_runtime.h>

// out[b, q, dv] = (1/SK) * sum_k value[b, k, dv]
// (q and k are the same broadcast scalar -> all logits equal -> softmax uniform
//  -> output = mean of value over SK, independent of query and q_param.)
//
// Serial read -> write phases (overlap measurably degrades combined throughput
// on this chip). Reduce kernel is pure (no atomics/fences: R12's 3.2us).
// Broadcast does the 8-way combine in a single-warp prologue, then streams
// stores (R13 showed the write phase compresses with a thinner prologue).

#define B   16
#define SQ  2048
#define SK  2048
#define DV  128
#define SPB 8                    // splits (CTAs) per batch in reduce
#define RPC (SK / SPB)           // 256 rows per reduce CTA

__device__ float4 g_part[B * SPB * 32];   // per-(b,split) partial row (512B)

// grid (B, SPB) = 128 CTAs, block 512. Each CTA reduces 256 rows.
// Each thread: 16 independent float4 loads, fully unrolled (MLP=16).
__global__ void __launch_bounds__(512)
reduce_kernel(const float4* __restrict__ value) {
    const int b   = blockIdx.x;
    const int sp  = blockIdx.y;
    const int tid = threadIdx.x;
    const int dv4 = tid & 31;            // float4 column
    const int rg  = tid >> 5;            // 0..15

    const float4* base = value + ((size_t)b * SK + sp * RPC + rg) * (DV / 4) + dv4;

    float4 v[16];
    #pragma unroll
    for (int k = 0; k < 16; ++k) {
        v[k] = base[(size_t)k * 16 * (DV / 4)];
    }
    float4 s = v[0];
    #pragma unroll
    for (int k = 1; k < 16; ++k) {
        s.x += v[k].x; s.y += v[k].y; s.z += v[k].z; s.w += v[k].w;
    }

    __shared__ float4 tmp[512];
    tmp[tid] = s;
    __syncthreads();

    if (tid < 32) {
        float4 a = tmp[tid];
        #pragma unroll
        for (int g = 1; g < 16; ++g) {
            float4 w = tmp[g * 32 + tid];
            a.x += w.x; a.y += w.y; a.z += w.z; a.w += w.w;
        }
        g_part[(b * SPB + sp) * 32 + tid] = a;
    }
}

// grid (16, B) = 256 CTAs, block 256. Each CTA writes 128 rows of batch b.
// Prologue: warp 0 combines the 8 partials for its column (8 unrolled L2
// loads), scales, publishes to smem. Then 16 independent STG.128 per thread.
__global__ void __launch_bounds__(256)
broadcast_kernel(float4* __restrict__ out) {
    const int b     = blockIdx.y;
    const int chunk = blockIdx.x;         // 128-row chunk
    const int tid   = threadIdx.x;
    const int dv4   = tid & 31;
    const int rg    = tid >> 5;           // 0..7

    __shared__ float4 fin[32];

    float4* o = out + ((size_t)b * SQ + chunk * 128 + rg) * (DV / 4) + dv4;

    cudaGridDependencySynchronize();

    if (tid < 32) {
        const float4* p = &g_part[b * SPB * 32 + tid];
        float4 v[SPB];
        #pragma unroll
        for (int sp = 0; sp < SPB; ++sp) {
            v[sp] = p[sp * 32];
        }
        float4 a = v[0];
        #pragma unroll
        for (int sp = 1; sp < SPB; ++sp) {
            a.x += v[sp].x; a.y += v[sp].y; a.z += v[sp].z; a.w += v[sp].w;
        }
        const float inv = 1.0f / (float)SK;
        a.x *= inv; a.y *= inv; a.z *= inv; a.w *= inv;
        fin[tid] = a;
    }
    __syncthreads();

    const float4 v = fin[dv4];
    #pragma unroll
    for (int i = 0; i < 16; ++i) {
        o[(size_t)i * 8 * (DV / 4)] = v;
    }
}

extern "C" void kernel_launch(void* const* d_in, const int* in_sizes, int n_in,
                              void* d_out, int out_size) {
    // inputs: query[B,SQ,D], key[B,SK,D], value[B,SK,DV], q_param[1,1]
    const float4* value = (const float4*)d_in[2];
    float4* out = (float4*)d_out;

    {
        dim3 rgrid(B, SPB);
        reduce_kernel<<<rgrid, 512>>>(value);
    }

    {
        cudaLaunchConfig_t cfg = {};
        cfg.gridDim  = dim3(16, B, 1);
        cfg.blockDim = dim3(256, 1, 1);
        cfg.dynamicSmemBytes = 0;
        cfg.stream = 0;

        cudaLaunchAttribute attr[1];
        attr[0].id = cudaLaunchAttributeProgrammaticStreamSerialization;
        attr[0].val.programmaticStreamSerializationAllowed = 1;
        cfg.attrs = attr;
        cfg.numAttrs = 1;

        cudaLaunchKernelEx(&cfg, broadcast_kernel, out);
    }
}

// round 15
// speedup vs baseline: 1.2333x; 1.0424x over previous
#include <cuda_runtime.h>

// out[b, q, dv] = (1/SK) * sum_k value[b, k, dv]
// (q and k are the same broadcast scalar -> all logits equal -> softmax uniform
//  -> output = mean of value over SK, independent of query and q_param.)
//
// Serial read -> write phases. Reduce CTAs REDG-accumulate their scaled
// partials straight into g_final (no g_part, no fences, no combine tail).
// Broadcast = thin prologue (one 512B load) + 4 STG.128/thread (the 6.66us
// write-phase shape measured in R13). Last broadcast CTA re-zeroes g_final
// for graph replay after all prologue reads are provably done.

#define B   16
#define SQ  2048
#define SK  2048
#define DV  128
#define SPB 8                    // splits (CTAs) per batch in reduce
#define RPC (SK / SPB)           // 256 rows per reduce CTA
#define BGRID_X 64               // broadcast CTAs per batch (32-row chunks)
#define NBCAST (BGRID_X * B)     // 1024

__device__ float g_final[B * DV];     // accumulated scaled mean rows (zero-init)
__device__ int   g_done;              // broadcast completion counter (zero-init)

// grid (B, SPB) = 128 CTAs, block 512. Each CTA reduces 256 rows with 16
// fully-unrolled independent float4 loads per thread, then REDG-adds its
// scaled 512B partial into g_final.
__global__ void __launch_bounds__(512)
reduce_kernel(const float4* __restrict__ value) {
    const int b   = blockIdx.x;
    const int sp  = blockIdx.y;
    const int tid = threadIdx.x;
    const int dv4 = tid & 31;            // float4 column
    const int rg  = tid >> 5;            // 0..15

    const float4* base = value + ((size_t)b * SK + sp * RPC + rg) * (DV / 4) + dv4;

    float4 v[16];
    #pragma unroll
    for (int k = 0; k < 16; ++k) {
        v[k] = base[(size_t)k * 16 * (DV / 4)];
    }
    float4 s = v[0];
    #pragma unroll
    for (int k = 1; k < 16; ++k) {
        s.x += v[k].x; s.y += v[k].y; s.z += v[k].z; s.w += v[k].w;
    }

    __shared__ float4 tmp[512];
    tmp[tid] = s;
    __syncthreads();

    if (tid < 32) {
        float4 a = tmp[tid];
        #pragma unroll
        for (int g = 1; g < 16; ++g) {
            float4 w = tmp[g * 32 + tid];
            a.x += w.x; a.y += w.y; a.z += w.z; a.w += w.w;
        }
        const float inv = 1.0f / (float)SK;
        a.x *= inv; a.y *= inv; a.z *= inv; a.w *= inv;

        float* dst = &g_final[b * DV + tid * 4];
        asm volatile("red.global.add.f32 [%0], %1;"     :: "l"(dst + 0), "f"(a.x) : "memory");
        asm volatile("red.global.add.f32 [%0], %1;"     :: "l"(dst + 1), "f"(a.y) : "memory");
        asm volatile("red.global.add.f32 [%0], %1;"     :: "l"(dst + 2), "f"(a.z) : "memory");
        asm volatile("red.global.add.f32 [%0], %1;"     :: "l"(dst + 3), "f"(a.w) : "memory");
    }
}

// grid (64, B) = 1024 CTAs, block 256. PDL sync -> load 512B final row ->
// 4 STG.128 per thread (32 output rows per CTA). Last CTA re-zeroes g_final.
__global__ void __launch_bounds__(256)
broadcast_kernel(float4* __restrict__ out) {
    const int b     = blockIdx.y;
    const int chunk = blockIdx.x;         // 32-row chunk
    const int tid   = threadIdx.x;
    const int dv4   = tid & 31;
    const int rg    = tid >> 5;           // 0..7

    __shared__ float4 fin[32];
    __shared__ int s_last;

    float4* o = out + ((size_t)b * SQ + chunk * 32 + rg) * (DV / 4) + dv4;

    cudaGridDependencySynchronize();

    if (tid < 32) fin[tid] = reinterpret_cast<const float4*>(g_final)[b * 32 + tid];
    __syncthreads();

    const float4 v = fin[dv4];
    #pragma unroll
    for (int i = 0; i < 4; ++i) {
        o[(size_t)i * 8 * (DV / 4)] = v;
    }

    // Replay reset: the 1024th CTA to finish re-zeroes g_final. Every CTA's
    // prologue read precedes its counter bump, so all reads are done.
    if (tid == 0) s_last = (atomicAdd(&g_done, 1) == NBCAST - 1);
    __syncthreads();
    if (s_last) {
        float4 z = make_float4(0.f, 0.f, 0.f, 0.f);
        for (int i = tid; i < B * DV / 4; i += 256) {
            reinterpret_cast<float4*>(g_final)[i] = z;
        }
        if (tid == 0) g_done = 0;
    }
}

extern "C" void kernel_launch(void* const* d_in, const int* in_sizes, int n_in,
                              void* d_out, int out_size) {
    // inputs: query[B,SQ,D], key[B,SK,D], value[B,SK,DV], q_param[1,1]
    const float4* value = (const float4*)d_in[2];
    float4* out = (float4*)d_out;

    {
        dim3 rgrid(B, SPB);
        reduce_kernel<<<rgrid, 512>>>(value);
    }

    {
        cudaLaunchConfig_t cfg = {};
        cfg.gridDim  = dim3(BGRID_X, B, 1);
        cfg.blockDim = dim3(256, 1, 1);
        cfg.dynamicSmemBytes = 0;
        cfg.stream = 0;

        cudaLaunchAttribute attr[1];
        attr[0].id = cudaLaunchAttributeProgrammaticStreamSerialization;
        attr[0].val.programmaticStreamSerializationAllowed = 1;
        cfg.attrs = attr;
        cfg.numAttrs = 1;

        cudaLaunchKernelEx(&cfg, broadcast_kernel, out);
    }
}